// round 7
// baseline (speedup 1.0000x reference)
#include <cuda_runtime.h>

// Fixed shapes: B=4, C=256, H=W=160, CPS=16 -> nv=nh=10, N=100, NPAT=400/branch
#define HH   160
#define WW   160
#define CC   256
#define NPAT 400
#define ENC  128

__device__ float g_conv_out[2 * NPAT * 256];   // [branch][patch][pix]
__device__ float g_h1[2 * NPAT * 256];         // hidden activations
__device__ float g_emb[2 * NPAT * ENC];        // [branch][patch][enc]
__device__ float g_e2T[4 * 128 * 100];         // e2 transposed: [b][d][n]

// ---------------------------------------------------------------------------
// Kernel A: channel-reduce conv + bias + relu. K split 4 ways (measured best).
// 800 blocks x 256 threads; block = 64 float4 outputs of one branch.
// ---------------------------------------------------------------------------
__global__ void __launch_bounds__(256) conv_kernel(
    const float* __restrict__ f1, const float* __restrict__ f2,
    const float* __restrict__ w_img, const float* __restrict__ b_img,
    const float* __restrict__ w_dep, const float* __restrict__ b_dep)
{
    __shared__ float  ws[256];
    __shared__ float4 part[4][64];
    __shared__ float  bias_s;

    const int t      = threadIdx.x;
    const int branch = blockIdx.x / 400;
    const int item0  = (blockIdx.x % 400) * 64;

    const float* wsrc = branch ? w_dep : w_img;
    ws[t] = wsrc[t];
    if (t == 0) bias_s = branch ? b_dep[0] : b_img[0];
    __syncthreads();

    const int kg = t >> 6;        // channel group 0..3
    const int ol = t & 63;
    const int r  = item0 + ol;    // 0..25599 (float4 items per branch)
    const int b  = r / 6400;      // 160*40 float4 per image
    const int r2 = r % 6400;
    const int h  = r2 / 40;
    const int w0 = (r2 % 40) * 4;

    const float* feat  = branch ? f2 : f1;
    const float4* base = (const float4*)(feat + (size_t)b * CC * HH * WW + h * WW + w0)
                         + (size_t)kg * 64 * 6400;   // channel stride = 6400 f4

    float4 acc = make_float4(0.f, 0.f, 0.f, 0.f);
    #pragma unroll 16
    for (int c = 0; c < 64; c++) {
        float4 v = base[c * 6400];
        float wc = ws[kg * 64 + c];
        acc.x = fmaf(v.x, wc, acc.x);
        acc.y = fmaf(v.y, wc, acc.y);
        acc.z = fmaf(v.z, wc, acc.z);
        acc.w = fmaf(v.w, wc, acc.w);
    }
    part[kg][ol] = acc;
    __syncthreads();

    if (t < 64) {
        float4 p0 = part[0][t], p1 = part[1][t], p2 = part[2][t], p3 = part[3][t];
        const float bb = bias_s;
        float4 o4;
        o4.x = fmaxf(p0.x + p1.x + p2.x + p3.x + bb, 0.f);
        o4.y = fmaxf(p0.y + p1.y + p2.y + p3.y + bb, 0.f);
        o4.z = fmaxf(p0.z + p1.z + p2.z + p3.z + bb, 0.f);
        o4.w = fmaxf(p0.w + p1.w + p2.w + p3.w + bb, 0.f);

        const int rr  = item0 + t;
        const int bb2 = rr / 6400;
        const int rr2 = rr % 6400;
        const int hh  = rr2 / 40;
        const int ww0 = (rr2 % 40) * 4;
        const int p   = bb2 * 100 + (hh >> 4) * 10 + (ww0 >> 4);
        const int pix = (hh & 15) * 16 + (ww0 & 15);
        *(float4*)&g_conv_out[(size_t)branch * NPAT * 256 + p * 256 + pix] = o4;
    }
}

// ---------------------------------------------------------------------------
// Kernel B1: GEMM1 + relu.  h1[p][o] = relu( x[p] . w1[o] ),  o in [0,256)
// Grid 200 = branch(2) x out-tile(4, 64 wide) x patch-tile(25, 16 tall).
// 128 threads: ox = t&15 (4 outputs), py = t>>4 (2 patches) -> 8 FMA per wv.
// ---------------------------------------------------------------------------
#define G1_SMEM_BYTES ((256 * 17 + 256 * 64) * 4)

__global__ void __launch_bounds__(128) gemm1_kernel(
    const float* __restrict__ w1_img, const float* __restrict__ w1_dep)
{
    extern __shared__ float sm[];
    float* as_ = sm;             // [256][17]   asT[k][p]
    float* ws_ = sm + 256 * 17;  // [256][64]   swizzled wsT[k][o]

    const int t      = threadIdx.x;
    const int branch = blockIdx.x / 100;
    const int rr     = blockIdx.x % 100;
    const int ot     = rr & 3;
    const int pt     = rr >> 2;
    const int p0     = branch * NPAT + pt * 16;
    const int o0     = ot * 64;

    const float* w1 = branch ? w1_dep : w1_img;

    #pragma unroll
    for (int j = 0; j < 8; j++) {
        const int idx4 = j * 128 + t;
        const int p    = idx4 >> 6;
        const int k4   = idx4 & 63;
        float4 v = *(const float4*)&g_conv_out[(size_t)(p0 + p) * 256 + k4 * 4];
        as_[(k4 * 4 + 0) * 17 + p] = v.x;
        as_[(k4 * 4 + 1) * 17 + p] = v.y;
        as_[(k4 * 4 + 2) * 17 + p] = v.z;
        as_[(k4 * 4 + 3) * 17 + p] = v.w;
    }
    {
        const int k4 = t & 63;
        const int og = t >> 6;   // 0..1
        #pragma unroll
        for (int j = 0; j < 8; j++) {
            const int ob = og * 32 + j * 4;
            const int o4 = og * 8 + j;
            float4 v0 = *(const float4*)&w1[(size_t)(o0 + ob + 0) * 256 + k4 * 4];
            float4 v1 = *(const float4*)&w1[(size_t)(o0 + ob + 1) * 256 + k4 * 4];
            float4 v2 = *(const float4*)&w1[(size_t)(o0 + ob + 2) * 256 + k4 * 4];
            float4 v3 = *(const float4*)&w1[(size_t)(o0 + ob + 3) * 256 + k4 * 4];
            float4 t0 = make_float4(v0.x, v1.x, v2.x, v3.x);
            float4 t1 = make_float4(v0.y, v1.y, v2.y, v3.y);
            float4 t2 = make_float4(v0.z, v1.z, v2.z, v3.z);
            float4 t3 = make_float4(v0.w, v1.w, v2.w, v3.w);
            const int kb = k4 * 4;
            *(float4*)&ws_[(kb + 0) * 64 + ((o4 ^ ((kb + 0) & 15)) << 2)] = t0;
            *(float4*)&ws_[(kb + 1) * 64 + ((o4 ^ ((kb + 1) & 15)) << 2)] = t1;
            *(float4*)&ws_[(kb + 2) * 64 + ((o4 ^ ((kb + 2) & 15)) << 2)] = t2;
            *(float4*)&ws_[(kb + 3) * 64 + ((o4 ^ ((kb + 3) & 15)) << 2)] = t3;
        }
    }
    __syncthreads();

    const int ox = t & 15;
    const int py = t >> 4;   // 0..7 -> patches 2py, 2py+1
    float a00 = 0.f, a01 = 0.f, a02 = 0.f, a03 = 0.f;
    float a10 = 0.f, a11 = 0.f, a12 = 0.f, a13 = 0.f;
    #pragma unroll 8
    for (int k = 0; k < 256; k++) {
        const float4 wv = *(const float4*)&ws_[k * 64 + ((ox ^ (k & 15)) << 2)];
        const float  x0 = as_[k * 17 + py * 2];
        const float  x1 = as_[k * 17 + py * 2 + 1];
        a00 = fmaf(x0, wv.x, a00); a01 = fmaf(x0, wv.y, a01);
        a02 = fmaf(x0, wv.z, a02); a03 = fmaf(x0, wv.w, a03);
        a10 = fmaf(x1, wv.x, a10); a11 = fmaf(x1, wv.y, a11);
        a12 = fmaf(x1, wv.z, a12); a13 = fmaf(x1, wv.w, a13);
    }
    const int gp = p0 + py * 2;
    float4 r0 = make_float4(fmaxf(a00, 0.f), fmaxf(a01, 0.f), fmaxf(a02, 0.f), fmaxf(a03, 0.f));
    float4 r1 = make_float4(fmaxf(a10, 0.f), fmaxf(a11, 0.f), fmaxf(a12, 0.f), fmaxf(a13, 0.f));
    *(float4*)&g_h1[(size_t)gp * 256 + o0 + ox * 4]       = r0;
    *(float4*)&g_h1[(size_t)(gp + 1) * 256 + o0 + ox * 4] = r1;
}

// ---------------------------------------------------------------------------
// Kernel B2: GEMM2 + LayerNorm.  y[p][o] = h1[p] . w2[o],  o in [0,128)
// Grid 100 = branch(2) x patch-tile(50, 8 tall). 128 threads.
// Branch 1 additionally writes the transposed copy e2T[b][d][n] for logits.
// ---------------------------------------------------------------------------
#define G2_SMEM_BYTES ((256 * 9 + 256 * 128) * 4)

__global__ void __launch_bounds__(128) gemm2_kernel(
    const float* __restrict__ w2_img, const float* __restrict__ g_img,
    const float* __restrict__ be_img,
    const float* __restrict__ w2_dep, const float* __restrict__ g_dep,
    const float* __restrict__ be_dep)
{
    extern __shared__ float sm[];
    float* as_ = sm;             // [256][9]
    float* ws_ = sm + 256 * 9;   // [256][128] swizzled

    const int t      = threadIdx.x;
    const int branch = blockIdx.x / 50;
    const int pt     = blockIdx.x % 50;
    const int p0     = branch * NPAT + pt * 8;

    const float* w2 = branch ? w2_dep : w2_img;

    #pragma unroll
    for (int j = 0; j < 4; j++) {
        const int idx4 = j * 128 + t;
        const int p    = idx4 >> 6;
        const int k4   = idx4 & 63;
        float4 v = *(const float4*)&g_h1[(size_t)(p0 + p) * 256 + k4 * 4];
        as_[(k4 * 4 + 0) * 9 + p] = v.x;
        as_[(k4 * 4 + 1) * 9 + p] = v.y;
        as_[(k4 * 4 + 2) * 9 + p] = v.z;
        as_[(k4 * 4 + 3) * 9 + p] = v.w;
    }
    {
        const int k4 = t & 63;
        const int og = t >> 6;   // 0..1
        #pragma unroll
        for (int j = 0; j < 16; j++) {
            const int ob = og * 64 + j * 4;
            const int o4 = og * 16 + j;
            float4 v0 = *(const float4*)&w2[(size_t)(ob + 0) * 256 + k4 * 4];
            float4 v1 = *(const float4*)&w2[(size_t)(ob + 1) * 256 + k4 * 4];
            float4 v2 = *(const float4*)&w2[(size_t)(ob + 2) * 256 + k4 * 4];
            float4 v3 = *(const float4*)&w2[(size_t)(ob + 3) * 256 + k4 * 4];
            float4 t0 = make_float4(v0.x, v1.x, v2.x, v3.x);
            float4 t1 = make_float4(v0.y, v1.y, v2.y, v3.y);
            float4 t2 = make_float4(v0.z, v1.z, v2.z, v3.z);
            float4 t3 = make_float4(v0.w, v1.w, v2.w, v3.w);
            const int kb = k4 * 4;
            *(float4*)&ws_[(kb + 0) * 128 + ((o4 ^ ((kb + 0) & 31)) << 2)] = t0;
            *(float4*)&ws_[(kb + 1) * 128 + ((o4 ^ ((kb + 1) & 31)) << 2)] = t1;
            *(float4*)&ws_[(kb + 2) * 128 + ((o4 ^ ((kb + 2) & 31)) << 2)] = t2;
            *(float4*)&ws_[(kb + 3) * 128 + ((o4 ^ ((kb + 3) & 31)) << 2)] = t3;
        }
    }
    __syncthreads();

    const int ox = t & 31;   // lane
    const int py = t >> 5;   // warp -> patches 2py, 2py+1
    float a00 = 0.f, a01 = 0.f, a02 = 0.f, a03 = 0.f;
    float a10 = 0.f, a11 = 0.f, a12 = 0.f, a13 = 0.f;
    #pragma unroll 4
    for (int k = 0; k < 256; k++) {
        const float4 wv = *(const float4*)&ws_[k * 128 + ((ox ^ (k & 31)) << 2)];
        const float  x0 = as_[k * 9 + py * 2];
        const float  x1 = as_[k * 9 + py * 2 + 1];
        a00 = fmaf(x0, wv.x, a00); a01 = fmaf(x0, wv.y, a01);
        a02 = fmaf(x0, wv.z, a02); a03 = fmaf(x0, wv.w, a03);
        a10 = fmaf(x1, wv.x, a10); a11 = fmaf(x1, wv.y, a11);
        a12 = fmaf(x1, wv.z, a12); a13 = fmaf(x1, wv.w, a13);
    }

    float sA = a00 + a01 + a02 + a03;
    float qA = a00 * a00 + a01 * a01 + a02 * a02 + a03 * a03;
    float sB = a10 + a11 + a12 + a13;
    float qB = a10 * a10 + a11 * a11 + a12 * a12 + a13 * a13;
    #pragma unroll
    for (int off = 16; off > 0; off >>= 1) {
        sA += __shfl_xor_sync(0xffffffffu, sA, off);
        qA += __shfl_xor_sync(0xffffffffu, qA, off);
        sB += __shfl_xor_sync(0xffffffffu, sB, off);
        qB += __shfl_xor_sync(0xffffffffu, qB, off);
    }
    const float mA = sA * (1.f / 128.f);
    const float mB = sB * (1.f / 128.f);
    const float rA = rsqrtf(qA * (1.f / 128.f) - mA * mA + 1e-5f);
    const float rB = rsqrtf(qB * (1.f / 128.f) - mB * mB + 1e-5f);

    const float* lg = branch ? g_dep  : g_img;
    const float* lb = branch ? be_dep : be_img;
    const float4 gv = *(const float4*)&lg[ox * 4];
    const float4 bv = *(const float4*)&lb[ox * 4];

    float4 oA, oB;
    oA.x = (a00 - mA) * rA * gv.x + bv.x;  oA.y = (a01 - mA) * rA * gv.y + bv.y;
    oA.z = (a02 - mA) * rA * gv.z + bv.z;  oA.w = (a03 - mA) * rA * gv.w + bv.w;
    oB.x = (a10 - mB) * rB * gv.x + bv.x;  oB.y = (a11 - mB) * rB * gv.y + bv.y;
    oB.z = (a12 - mB) * rB * gv.z + bv.z;  oB.w = (a13 - mB) * rB * gv.w + bv.w;

    const int gp = p0 + py * 2;
    *(float4*)&g_emb[(size_t)gp * 128 + ox * 4]       = oA;
    *(float4*)&g_emb[(size_t)(gp + 1) * 128 + ox * 4] = oB;

    if (branch == 1) {
        // transposed copy for logits: e2T[(b*128 + d)*100 + n]
        const int lpA = pt * 8 + py * 2;       // local patch 0..399
        const int lpB = lpA + 1;
        const int bA = lpA / 100, nA = lpA % 100;
        const int bB = lpB / 100, nB = lpB % 100;
        const int d0 = ox * 4;
        g_e2T[(bA * 128 + d0 + 0) * 100 + nA] = oA.x;
        g_e2T[(bA * 128 + d0 + 1) * 100 + nA] = oA.y;
        g_e2T[(bA * 128 + d0 + 2) * 100 + nA] = oA.z;
        g_e2T[(bA * 128 + d0 + 3) * 100 + nA] = oA.w;
        g_e2T[(bB * 128 + d0 + 0) * 100 + nB] = oB.x;
        g_e2T[(bB * 128 + d0 + 1) * 100 + nB] = oB.y;
        g_e2T[(bB * 128 + d0 + 2) * 100 + nB] = oB.z;
        g_e2T[(bB * 128 + d0 + 3) * 100 + nB] = oB.w;
    }
}

// ---------------------------------------------------------------------------
// Kernel C: logits via e2T.  Grid (50 n-pairs, 4 batches) = 200 blocks x 128.
// Block = 2 e1 rows (smem broadcast). Thread t = m; loop over d reads
// e2T[(b*128+d)*100 + t] -> fully coalesced warp loads. 2 FMA per load.
// ---------------------------------------------------------------------------
__global__ void __launch_bounds__(128) logits_kernel(
    const float* __restrict__ logit_scale, float* __restrict__ out)
{
    __shared__ float e1s[2][128];

    const int t  = threadIdx.x;
    const int b  = blockIdx.y;
    const int n0 = blockIdx.x * 2;

    if (t < 64) {
        const int r  = t >> 5;
        const int c4 = t & 31;
        *(float4*)&e1s[r][c4 * 4] =
            *(const float4*)&g_emb[(size_t)(b * 100 + n0 + r) * 128 + c4 * 4];
    }
    __syncthreads();

    if (t < 100) {
        const float scale = expf(logit_scale[0]);
        const float* e2c = g_e2T + (size_t)b * 128 * 100 + t;
        float a0 = 0.f, a1 = 0.f;
        #pragma unroll 16
        for (int d = 0; d < 128; d++) {
            const float v = e2c[d * 100];
            a0 = fmaf(e1s[0][d], v, a0);
            a1 = fmaf(e1s[1][d], v, a1);
        }
        const float v0 = scale * a0;
        const float v1 = scale * a1;
        float* o1 = out + b * 10000;
        float* o2 = out + 40000 + b * 10000;
        o1[(n0 + 0) * 100 + t] = v0;
        o1[(n0 + 1) * 100 + t] = v1;
        o2[t * 100 + n0 + 0] = v0;
        o2[t * 100 + n0 + 1] = v1;
    }
}

// ---------------------------------------------------------------------------
// Inputs: feat_c1, feat_c2, mask_c1, img_conv_w, img_conv_b, img_w1, img_w2,
// img_ln_g, img_ln_b, depth_conv_w, depth_conv_b, depth_w1, depth_w2,
// depth_ln_g, depth_ln_b, logit_scale
// ---------------------------------------------------------------------------
extern "C" void kernel_launch(void* const* d_in, const int* in_sizes, int n_in,
                              void* d_out, int out_size)
{
    cudaFuncSetAttribute(gemm1_kernel, cudaFuncAttributeMaxDynamicSharedMemorySize, G1_SMEM_BYTES);
    cudaFuncSetAttribute(gemm2_kernel, cudaFuncAttributeMaxDynamicSharedMemorySize, G2_SMEM_BYTES);

    conv_kernel<<<800, 256>>>((const float*)d_in[0], (const float*)d_in[1],
                              (const float*)d_in[3],  (const float*)d_in[4],
                              (const float*)d_in[9],  (const float*)d_in[10]);

    gemm1_kernel<<<200, 128, G1_SMEM_BYTES>>>((const float*)d_in[5], (const float*)d_in[11]);

    gemm2_kernel<<<100, 128, G2_SMEM_BYTES>>>((const float*)d_in[6],  (const float*)d_in[7],
                                              (const float*)d_in[8],
                                              (const float*)d_in[12], (const float*)d_in[13],
                                              (const float*)d_in[14]);

    logits_kernel<<<dim3(50, 4), 128>>>((const float*)d_in[15], (float*)d_out);
}